// round 2
// baseline (speedup 1.0000x reference)
#include <cuda_runtime.h>
#include <cstdint>

#define N_NODES 50000
#define N_EDGES 800000
#define IN_CH 256
#define OUT_CH 64
#define HEADS 4
#define HC 256  // HEADS*OUT_CH

// ---------------- scratch (device globals; no allocation allowed) ----------------
__device__ __align__(128) float g_xh[(size_t)N_NODES * HC];        // 51.2 MB projected features
__device__ __align__(128) float g_asrc[N_NODES * HEADS];
__device__ __align__(128) float g_adst[N_NODES * HEADS];
__device__ __align__(128) int   g_deg[N_NODES];
__device__ __align__(128) int   g_ctr[N_NODES];
__device__ __align__(128) int   g_rowptr[N_NODES + 1];
__device__ __align__(128) int   g_col[N_EDGES];
__device__ __align__(128) float g_Wc[IN_CH * HC];                  // combined weight [f][h*64+c]
__device__ __align__(128) float g_p[2 * IN_CH * HEADS];            // folded att: src then dst

// ---------------- small prep kernels ----------------

// Wc[f*256 + h*64+c] = weight[h][f][c]
__global__ void prep_w_kernel(const float* __restrict__ w) {
    int idx = blockIdx.x * blockDim.x + threadIdx.x;   // < 65536
    int f = idx >> 8;
    int hc = idx & 255;
    int h = hc >> 6;
    int c = hc & 63;
    g_Wc[idx] = w[h * (IN_CH * OUT_CH) + f * OUT_CH + c];
}

// p_src[f*4+h] = sum_c W[h][f][c] * att_src[h][c]  (same for dst)
__global__ void prep_p_kernel(const float* __restrict__ w,
                              const float* __restrict__ as,
                              const float* __restrict__ ad) {
    int t = blockIdx.x * blockDim.x + threadIdx.x;     // < 1024
    if (t >= IN_CH * HEADS) return;
    int f = t >> 2, h = t & 3;
    float ssum = 0.f, dsum = 0.f;
    const float* wr = w + h * (IN_CH * OUT_CH) + f * OUT_CH;
    const float* asr = as + h * OUT_CH;
    const float* adr = ad + h * OUT_CH;
#pragma unroll 8
    for (int c = 0; c < OUT_CH; c++) {
        float wv = wr[c];
        ssum += wv * asr[c];
        dsum += wv * adr[c];
    }
    g_p[t] = ssum;
    g_p[IN_CH * HEADS + t] = dsum;
}

__global__ void zero_kernel() {
    int i = blockIdx.x * blockDim.x + threadIdx.x;
    if (i < N_NODES) { g_deg[i] = 0; g_ctr[i] = 0; }
}

// ---------------- CSR build ----------------
// edge_index arrives as int32 (harness converts int64 -> int32), layout [2][E].

__global__ void hist_kernel(const int* __restrict__ ei) {
    int e = blockIdx.x * blockDim.x + threadIdx.x;
    if (e < N_EDGES) atomicAdd(&g_deg[ei[e]], 1);
}

__global__ void scan_kernel() {
    __shared__ int sh[1024];
    const int CH = (N_NODES + 1023) / 1024;  // 49
    int t = threadIdx.x;
    int beg = t * CH;
    int sum = 0;
    for (int i = 0; i < CH; i++) {
        int idx = beg + i;
        if (idx < N_NODES) sum += g_deg[idx];
    }
    sh[t] = sum;
    __syncthreads();
    // Kogge-Stone inclusive scan
    for (int off = 1; off < 1024; off <<= 1) {
        int v = (t >= off) ? sh[t - off] : 0;
        __syncthreads();
        sh[t] += v;
        __syncthreads();
    }
    int run = (t == 0) ? 0 : sh[t - 1];
    for (int i = 0; i < CH; i++) {
        int idx = beg + i;
        if (idx < N_NODES) {
            g_rowptr[idx] = run;
            run += g_deg[idx];
        }
    }
    if (t == 0) g_rowptr[N_NODES] = N_EDGES;
}

__global__ void scatter_kernel(const int* __restrict__ ei) {
    int e = blockIdx.x * blockDim.x + threadIdx.x;
    if (e < N_EDGES) {
        int r = ei[e];
        int c = ei[N_EDGES + e];
        int p = g_rowptr[r] + atomicAdd(&g_ctr[r], 1);
        g_col[p] = c;
    }
}

// ---------------- projection GEMM: x [N,256] x Wc [256,256] -> g_xh ----------------
// classic 128x128x8 SGEMM, 256 threads, 8x8 per thread.

#define BM 128
#define BN 128
#define BK 8

__global__ __launch_bounds__(256) void gemm_kernel(const float* __restrict__ A) {
    __shared__ float As[BK][BM + 4];
    __shared__ float Bs[BK][BN];
    int tid = threadIdx.x;
    int tx = tid & 15;
    int ty = tid >> 4;
    int block_row = blockIdx.x * BM;
    int block_col = blockIdx.y * BN;

    float acc[8][8];
#pragma unroll
    for (int i = 0; i < 8; i++)
#pragma unroll
        for (int j = 0; j < 8; j++) acc[i][j] = 0.f;

    int a_row = tid >> 1;
    int a_col = (tid & 1) * 4;
    int b_row = tid >> 5;
    int b_col = (tid & 31) * 4;

    for (int k0 = 0; k0 < IN_CH; k0 += BK) {
        int gr = block_row + a_row;
        float4 av = make_float4(0.f, 0.f, 0.f, 0.f);
        if (gr < N_NODES)
            av = *(const float4*)(A + (size_t)gr * IN_CH + k0 + a_col);
        As[a_col + 0][a_row] = av.x;
        As[a_col + 1][a_row] = av.y;
        As[a_col + 2][a_row] = av.z;
        As[a_col + 3][a_row] = av.w;

        float4 bv = *(const float4*)(g_Wc + (size_t)(k0 + b_row) * HC + block_col + b_col);
        *(float4*)&Bs[b_row][b_col] = bv;
        __syncthreads();

#pragma unroll
        for (int k = 0; k < BK; ++k) {
            float ra[8], rb[8];
#pragma unroll
            for (int i = 0; i < 8; i++) ra[i] = As[k][ty * 8 + i];
#pragma unroll
            for (int j = 0; j < 8; j++) rb[j] = Bs[k][tx * 8 + j];
#pragma unroll
            for (int i = 0; i < 8; i++)
#pragma unroll
                for (int j = 0; j < 8; j++) acc[i][j] += ra[i] * rb[j];
        }
        __syncthreads();
    }

#pragma unroll
    for (int i = 0; i < 8; i++) {
        int gr = block_row + ty * 8 + i;
        if (gr < N_NODES) {
            float* orow = g_xh + (size_t)gr * HC + block_col + tx * 8;
            *(float4*)(orow)     = make_float4(acc[i][0], acc[i][1], acc[i][2], acc[i][3]);
            *(float4*)(orow + 4) = make_float4(acc[i][4], acc[i][5], acc[i][6], acc[i][7]);
        }
    }
}

// ---------------- attention logits: alpha = x @ p (one warp per node) ----------------

__global__ __launch_bounds__(256) void alpha_kernel(const float* __restrict__ x) {
    int warp = (blockIdx.x * blockDim.x + threadIdx.x) >> 5;
    int lane = threadIdx.x & 31;
    if (warp >= N_NODES) return;
    const float* xr = x + (size_t)warp * IN_CH;
    float s[4] = {0.f, 0.f, 0.f, 0.f};
    float d[4] = {0.f, 0.f, 0.f, 0.f};
    for (int f = lane; f < IN_CH; f += 32) {
        float xv = xr[f];
        const float* ps = g_p + f * 4;
        const float* pd = g_p + IN_CH * HEADS + f * 4;
#pragma unroll
        for (int h = 0; h < 4; h++) {
            s[h] += xv * ps[h];
            d[h] += xv * pd[h];
        }
    }
#pragma unroll
    for (int off = 16; off > 0; off >>= 1) {
#pragma unroll
        for (int h = 0; h < 4; h++) {
            s[h] += __shfl_xor_sync(0xffffffffu, s[h], off);
            d[h] += __shfl_xor_sync(0xffffffffu, d[h], off);
        }
    }
    if (lane == 0) {
#pragma unroll
        for (int h = 0; h < 4; h++) {
            g_asrc[warp * 4 + h] = s[h];
            g_adst[warp * 4 + h] = d[h];
        }
    }
}

// ---------------- softmax + weighted gather aggregation (one warp per node) ----------------

__global__ __launch_bounds__(256) void aggregate_kernel(const float* __restrict__ bias,
                                                        float* __restrict__ out) {
    int warp = (blockIdx.x * blockDim.x + threadIdx.x) >> 5;
    int lane = threadIdx.x & 31;
    if (warp >= N_NODES) return;
    int head = lane >> 3;
    float ah = g_asrc[warp * 4 + head];
    int beg = g_rowptr[warp];
    int end = g_rowptr[warp + 1];

    // pass 1: online softmax (running max + scaled sum)
    float m = -1e30f, s = 0.f;
    for (int e = beg; e < end; ++e) {
        int c = g_col[e];
        float a = ah + g_adst[c * 4 + head];
        a = (a > 0.f) ? a : 0.2f * a;
        float nm = fmaxf(m, a);
        s = s * __expf(m - nm) + __expf(a - nm);
        m = nm;
    }
    float inv = 1.0f / fmaxf(s, 1e-16f);

    // pass 2: weighted gather
    float acc[8];
#pragma unroll
    for (int i = 0; i < 8; i++) acc[i] = 0.f;
    int chbase = lane * 8;
    for (int e = beg; e < end; ++e) {
        int c = g_col[e];
        float a = ah + g_adst[c * 4 + head];
        a = (a > 0.f) ? a : 0.2f * a;
        float w = __expf(a - m) * inv;
        const float4* src = (const float4*)(g_xh + (size_t)c * HC + chbase);
        float4 v0 = src[0];
        float4 v1 = src[1];
        acc[0] += w * v0.x; acc[1] += w * v0.y; acc[2] += w * v0.z; acc[3] += w * v0.w;
        acc[4] += w * v1.x; acc[5] += w * v1.y; acc[6] += w * v1.z; acc[7] += w * v1.w;
    }

    float4 b0 = *(const float4*)(bias + chbase);
    float4 b1 = *(const float4*)(bias + chbase + 4);
    float* orow = out + (size_t)warp * HC + chbase;
    *(float4*)(orow)     = make_float4(acc[0] + b0.x, acc[1] + b0.y, acc[2] + b0.z, acc[3] + b0.w);
    *(float4*)(orow + 4) = make_float4(acc[4] + b1.x, acc[5] + b1.y, acc[6] + b1.z, acc[7] + b1.w);
}

// ---------------- launch ----------------

extern "C" void kernel_launch(void* const* d_in, const int* in_sizes, int n_in,
                              void* d_out, int out_size) {
    const float* x    = (const float*)d_in[0];
    const int*   ei   = (const int*)d_in[1];
    const float* w    = (const float*)d_in[2];
    const float* asv  = (const float*)d_in[3];
    const float* adv  = (const float*)d_in[4];
    const float* bias = (const float*)d_in[5];
    float* out = (float*)d_out;

    // prep
    prep_w_kernel<<<(IN_CH * HC) / 256, 256>>>(w);
    prep_p_kernel<<<4, 256>>>(w, asv, adv);

    // CSR build
    zero_kernel<<<(N_NODES + 255) / 256, 256>>>();
    hist_kernel<<<(N_EDGES + 255) / 256, 256>>>(ei);
    scan_kernel<<<1, 1024>>>();
    scatter_kernel<<<(N_EDGES + 255) / 256, 256>>>(ei);

    // projection + attention logits
    dim3 ggrid((N_NODES + BM - 1) / BM, HC / BN);
    gemm_kernel<<<ggrid, 256>>>(x);
    alpha_kernel<<<(N_NODES * 32 + 255) / 256, 256>>>(x);

    // softmax + aggregate
    aggregate_kernel<<<(N_NODES * 32 + 255) / 256, 256>>>(bias, out);
}

// round 5
// speedup vs baseline: 1.4341x; 1.4341x over previous
#include <cuda_runtime.h>
#include <cuda_bf16.h>
#include <cstdint>

#define N_NODES 50000
#define N_EDGES 800000
#define IN_CH 256
#define OUT_CH 64
#define HEADS 4
#define HC 256  // HEADS*OUT_CH

// ---------------- scratch (device globals; no allocation allowed) ----------------
__device__ __align__(128) float g_xh[(size_t)N_NODES * HC];        // 51.2 MB projected features
__device__ __align__(128) float g_asrc[N_NODES * HEADS];
__device__ __align__(128) float g_adst[N_NODES * HEADS];
__device__ __align__(128) int   g_deg[N_NODES];
__device__ __align__(128) int   g_ctr[N_NODES];
__device__ __align__(128) int   g_rowptr[N_NODES + 1];
__device__ __align__(128) int   g_col[N_EDGES];
__device__ __align__(128) __nv_bfloat16 g_Whi[HC * IN_CH];         // [n][k] layout (k contiguous)
__device__ __align__(128) __nv_bfloat16 g_Wlo[HC * IN_CH];
__device__ __align__(128) float g_p[2 * IN_CH * HEADS];            // folded att: src then dst

// ---------------- small prep kernels ----------------

// Split W into bf16 hi/lo in [n][k] layout: n = h*64+c, k = f.
__global__ void prep_wsplit_kernel(const float* __restrict__ w) {
    int idx = blockIdx.x * blockDim.x + threadIdx.x;   // < 65536
    int n = idx >> 8;       // 0..255
    int k = idx & 255;      // 0..255
    int h = n >> 6;
    int c = n & 63;
    float v = w[h * (IN_CH * OUT_CH) + k * OUT_CH + c];
    __nv_bfloat16 hi = __float2bfloat16(v);
    __nv_bfloat16 lo = __float2bfloat16(v - __bfloat162float(hi));
    g_Whi[idx] = hi;
    g_Wlo[idx] = lo;
}

// p_src[f*4+h] = sum_c W[h][f][c] * att_src[h][c]  (same for dst)
__global__ void prep_p_kernel(const float* __restrict__ w,
                              const float* __restrict__ as,
                              const float* __restrict__ ad) {
    int t = blockIdx.x * blockDim.x + threadIdx.x;     // < 1024
    if (t >= IN_CH * HEADS) return;
    int f = t >> 2, h = t & 3;
    float ssum = 0.f, dsum = 0.f;
    const float* wr = w + h * (IN_CH * OUT_CH) + f * OUT_CH;
    const float* asr = as + h * OUT_CH;
    const float* adr = ad + h * OUT_CH;
#pragma unroll 8
    for (int c = 0; c < OUT_CH; c++) {
        float wv = wr[c];
        ssum += wv * asr[c];
        dsum += wv * adr[c];
    }
    g_p[t] = ssum;
    g_p[IN_CH * HEADS + t] = dsum;
}

__global__ void zero_kernel() {
    int i = blockIdx.x * blockDim.x + threadIdx.x;
    if (i < N_NODES) { g_deg[i] = 0; g_ctr[i] = 0; }
}

// ---------------- CSR build (edge_index is int32, [2][E]) ----------------

__global__ void hist_kernel(const int* __restrict__ ei) {
    int e = blockIdx.x * blockDim.x + threadIdx.x;
    if (e < N_EDGES) atomicAdd(&g_deg[ei[e]], 1);
}

__global__ void scan_kernel() {
    __shared__ int sh[1024];
    const int CH = (N_NODES + 1023) / 1024;  // 49
    int t = threadIdx.x;
    int beg = t * CH;
    int sum = 0;
    for (int i = 0; i < CH; i++) {
        int idx = beg + i;
        if (idx < N_NODES) sum += g_deg[idx];
    }
    sh[t] = sum;
    __syncthreads();
    for (int off = 1; off < 1024; off <<= 1) {
        int v = (t >= off) ? sh[t - off] : 0;
        __syncthreads();
        sh[t] += v;
        __syncthreads();
    }
    int run = (t == 0) ? 0 : sh[t - 1];
    for (int i = 0; i < CH; i++) {
        int idx = beg + i;
        if (idx < N_NODES) {
            g_rowptr[idx] = run;
            run += g_deg[idx];
        }
    }
    if (t == 0) g_rowptr[N_NODES] = N_EDGES;
}

__global__ void scatter_kernel(const int* __restrict__ ei) {
    int e = blockIdx.x * blockDim.x + threadIdx.x;
    if (e < N_EDGES) {
        int r = ei[e];
        int c = ei[N_EDGES + e];
        int p = g_rowptr[r] + atomicAdd(&g_ctr[r], 1);
        g_col[p] = c;
    }
}

// ---------------- HMMA projection GEMM: x [N,256] @ W^T -> g_xh [N,256] ----------------
// mma.sync.m16n8k16 bf16 with 2-term split: x@W ~= xhi@Whi + xhi@Wlo + xlo@Whi.
// CTA: 128 rows x 128 cols, 8 warps, each warp 32x64. K in 4 chunks of 64.
// SMEM row stride 144 B -> conflict-free fragment loads (banks 4*row+t all distinct).

#define GK 64
#define A_STRIDE 144                 // bytes per 64-col bf16 row (padded)
#define TILE_BYTES (128 * A_STRIDE)  // 18432
#define SM_AHI 0
#define SM_ALO (TILE_BYTES)
#define SM_BHI (2 * TILE_BYTES)
#define SM_BLO (3 * TILE_BYTES)
#define SM_TOTAL (4 * TILE_BYTES)    // 73728 B

__device__ __forceinline__ void mma16816(float* c, const uint32_t* a, uint32_t b0, uint32_t b1) {
    asm volatile(
        "mma.sync.aligned.m16n8k16.row.col.f32.bf16.bf16.f32 "
        "{%0,%1,%2,%3}, {%4,%5,%6,%7}, {%8,%9}, {%0,%1,%2,%3};"
        : "+f"(c[0]), "+f"(c[1]), "+f"(c[2]), "+f"(c[3])
        : "r"(a[0]), "r"(a[1]), "r"(a[2]), "r"(a[3]), "r"(b0), "r"(b1));
}

__global__ __launch_bounds__(256) void gemm_mma_kernel(const float* __restrict__ x) {
    extern __shared__ char smem[];
    int tid = threadIdx.x;
    int w = tid >> 5;
    int lane = tid & 31;
    int grp = lane >> 2;       // 0..7
    int t = lane & 3;          // 0..3
    int block_row = blockIdx.x * 128;
    int block_col = blockIdx.y * 128;

    int wm = (w & 3) * 32;     // warp row offset in CTA tile
    int wn = (w >> 2) * 64;    // warp col offset in CTA tile

    float acc[2][8][4];
#pragma unroll
    for (int mt = 0; mt < 2; mt++)
#pragma unroll
        for (int nt = 0; nt < 8; nt++)
#pragma unroll
            for (int q = 0; q < 4; q++) acc[mt][nt][q] = 0.f;

    for (int kc = 0; kc < IN_CH / GK; kc++) {
        // ---- load A chunk: x[block_row..+128][kc*64..+64] fp32 -> hi/lo bf16 ----
#pragma unroll
        for (int i = 0; i < 8; i++) {
            int id = tid + i * 256;          // 0..2047
            int row = id >> 4;               // 0..127
            int c4 = id & 15;                // float4 index within 64 cols
            int grow = block_row + row;
            float4 v = make_float4(0.f, 0.f, 0.f, 0.f);
            if (grow < N_NODES)
                v = *(const float4*)(x + (size_t)grow * IN_CH + kc * GK + c4 * 4);
            __nv_bfloat162 h01 = make_bfloat162(__float2bfloat16(v.x), __float2bfloat16(v.y));
            __nv_bfloat162 h23 = make_bfloat162(__float2bfloat16(v.z), __float2bfloat16(v.w));
            __nv_bfloat162 l01 = make_bfloat162(
                __float2bfloat16(v.x - __bfloat162float(h01.x)),
                __float2bfloat16(v.y - __bfloat162float(h01.y)));
            __nv_bfloat162 l23 = make_bfloat162(
                __float2bfloat16(v.z - __bfloat162float(h23.x)),
                __float2bfloat16(v.w - __bfloat162float(h23.y)));
            uint32_t bo = row * A_STRIDE + c4 * 8;
            *(uint2*)(smem + SM_AHI + bo) = make_uint2(*(uint32_t*)&h01, *(uint32_t*)&h23);
            *(uint2*)(smem + SM_ALO + bo) = make_uint2(*(uint32_t*)&l01, *(uint32_t*)&l23);
        }
        // ---- load B chunk: W{hi,lo}[block_col..+128][kc*64..+64] bf16 ----
#pragma unroll
        for (int i = 0; i < 4; i++) {
            int id = tid + i * 256;          // 0..1023 16B units
            int row = id >> 3;               // 0..127
            int u = id & 7;
            size_t goff = (size_t)(block_col + row) * IN_CH + kc * GK + u * 8;
            uint4 vh = *(const uint4*)(g_Whi + goff);
            uint4 vl = *(const uint4*)(g_Wlo + goff);
            uint32_t bo = row * A_STRIDE + u * 16;
            *(uint4*)(smem + SM_BHI + bo) = vh;
            *(uint4*)(smem + SM_BLO + bo) = vl;
        }
        __syncthreads();

        // ---- compute: 4 k16-steps ----
#pragma unroll
        for (int k16 = 0; k16 < 4; k16++) {
            int ko = k16 * 32;  // byte offset of this k16 within the 128B row
            uint32_t ah[2][4], al[2][4];
#pragma unroll
            for (int mt = 0; mt < 2; mt++) {
                int r0 = wm + mt * 16 + grp;
                uint32_t o00 = r0 * A_STRIDE + ko + t * 4;
                uint32_t o10 = (r0 + 8) * A_STRIDE + ko + t * 4;
                ah[mt][0] = *(const uint32_t*)(smem + SM_AHI + o00);
                ah[mt][1] = *(const uint32_t*)(smem + SM_AHI + o10);
                ah[mt][2] = *(const uint32_t*)(smem + SM_AHI + o00 + 16);
                ah[mt][3] = *(const uint32_t*)(smem + SM_AHI + o10 + 16);
                al[mt][0] = *(const uint32_t*)(smem + SM_ALO + o00);
                al[mt][1] = *(const uint32_t*)(smem + SM_ALO + o10);
                al[mt][2] = *(const uint32_t*)(smem + SM_ALO + o00 + 16);
                al[mt][3] = *(const uint32_t*)(smem + SM_ALO + o10 + 16);
            }
#pragma unroll
            for (int nt = 0; nt < 8; nt++) {
                int n0 = wn + nt * 8 + grp;
                uint32_t ob = n0 * A_STRIDE + ko + t * 4;
                uint32_t bh0 = *(const uint32_t*)(smem + SM_BHI + ob);
                uint32_t bh1 = *(const uint32_t*)(smem + SM_BHI + ob + 16);
                uint32_t bl0 = *(const uint32_t*)(smem + SM_BLO + ob);
                uint32_t bl1 = *(const uint32_t*)(smem + SM_BLO + ob + 16);
#pragma unroll
                for (int mt = 0; mt < 2; mt++) {
                    mma16816(acc[mt][nt], ah[mt], bh0, bh1);
                    mma16816(acc[mt][nt], ah[mt], bl0, bl1);
                    mma16816(acc[mt][nt], al[mt], bh0, bh1);
                }
            }
        }
        __syncthreads();
    }

    // ---- epilogue: write fragments to g_xh ----
#pragma unroll
    for (int mt = 0; mt < 2; mt++) {
        int gr0 = block_row + wm + mt * 16 + grp;
        int gr1 = gr0 + 8;
#pragma unroll
        for (int nt = 0; nt < 8; nt++) {
            int gc = block_col + wn + nt * 8 + t * 2;
            if (gr0 < N_NODES)
                *(float2*)(g_xh + (size_t)gr0 * HC + gc) = make_float2(acc[mt][nt][0], acc[mt][nt][1]);
            if (gr1 < N_NODES)
                *(float2*)(g_xh + (size_t)gr1 * HC + gc) = make_float2(acc[mt][nt][2], acc[mt][nt][3]);
        }
    }
}

// ---------------- attention logits: alpha = x @ p (one warp per node) ----------------

__global__ __launch_bounds__(256) void alpha_kernel(const float* __restrict__ x) {
    int warp = (blockIdx.x * blockDim.x + threadIdx.x) >> 5;
    int lane = threadIdx.x & 31;
    if (warp >= N_NODES) return;
    const float* xr = x + (size_t)warp * IN_CH;
    float s[4] = {0.f, 0.f, 0.f, 0.f};
    float d[4] = {0.f, 0.f, 0.f, 0.f};
    for (int f = lane; f < IN_CH; f += 32) {
        float xv = xr[f];
        const float* ps = g_p + f * 4;
        const float* pd = g_p + IN_CH * HEADS + f * 4;
#pragma unroll
        for (int h = 0; h < 4; h++) {
            s[h] += xv * ps[h];
            d[h] += xv * pd[h];
        }
    }
#pragma unroll
    for (int off = 16; off > 0; off >>= 1) {
#pragma unroll
        for (int h = 0; h < 4; h++) {
            s[h] += __shfl_xor_sync(0xffffffffu, s[h], off);
            d[h] += __shfl_xor_sync(0xffffffffu, d[h], off);
        }
    }
    if (lane == 0) {
#pragma unroll
        for (int h = 0; h < 4; h++) {
            g_asrc[warp * 4 + h] = s[h];
            g_adst[warp * 4 + h] = d[h];
        }
    }
}

// ---------------- softmax + weighted gather aggregation (one warp per node) ----------------

__global__ __launch_bounds__(256) void aggregate_kernel(const float* __restrict__ bias,
                                                        float* __restrict__ out) {
    int warp = (blockIdx.x * blockDim.x + threadIdx.x) >> 5;
    int lane = threadIdx.x & 31;
    if (warp >= N_NODES) return;
    int head = lane >> 3;
    float ah = g_asrc[warp * 4 + head];
    int beg = g_rowptr[warp];
    int end = g_rowptr[warp + 1];

    // pass 1: online softmax (running max + scaled sum)
    float m = -1e30f, s = 0.f;
    for (int e = beg; e < end; ++e) {
        int c = g_col[e];
        float a = ah + g_adst[c * 4 + head];
        a = (a > 0.f) ? a : 0.2f * a;
        float nm = fmaxf(m, a);
        s = s * __expf(m - nm) + __expf(a - nm);
        m = nm;
    }
    float inv = 1.0f / fmaxf(s, 1e-16f);

    // pass 2: weighted gather
    float acc[8];
#pragma unroll
    for (int i = 0; i < 8; i++) acc[i] = 0.f;
    int chbase = lane * 8;
    for (int e = beg; e < end; ++e) {
        int c = g_col[e];
        float a = ah + g_adst[c * 4 + head];
        a = (a > 0.f) ? a : 0.2f * a;
        float w = __expf(a - m) * inv;
        const float4* src = (const float4*)(g_xh + (size_t)c * HC + chbase);
        float4 v0 = src[0];
        float4 v1 = src[1];
        acc[0] += w * v0.x; acc[1] += w * v0.y; acc[2] += w * v0.z; acc[3] += w * v0.w;
        acc[4] += w * v1.x; acc[5] += w * v1.y; acc[6] += w * v1.z; acc[7] += w * v1.w;
    }

    float4 b0 = *(const float4*)(bias + chbase);
    float4 b1 = *(const float4*)(bias + chbase + 4);
    float* orow = out + (size_t)warp * HC + chbase;
    *(float4*)(orow)     = make_float4(acc[0] + b0.x, acc[1] + b0.y, acc[2] + b0.z, acc[3] + b0.w);
    *(float4*)(orow + 4) = make_float4(acc[4] + b1.x, acc[5] + b1.y, acc[6] + b1.z, acc[7] + b1.w);
}

// ---------------- launch ----------------

extern "C" void kernel_launch(void* const* d_in, const int* in_sizes, int n_in,
                              void* d_out, int out_size) {
    const float* x    = (const float*)d_in[0];
    const int*   ei   = (const int*)d_in[1];
    const float* w    = (const float*)d_in[2];
    const float* asv  = (const float*)d_in[3];
    const float* adv  = (const float*)d_in[4];
    const float* bias = (const float*)d_in[5];
    float* out = (float*)d_out;

    cudaFuncSetAttribute(gemm_mma_kernel, cudaFuncAttributeMaxDynamicSharedMemorySize, SM_TOTAL);

    // prep
    prep_wsplit_kernel<<<(HC * IN_CH) / 256, 256>>>(w);
    prep_p_kernel<<<4, 256>>>(w, asv, adv);

    // CSR build
    zero_kernel<<<(N_NODES + 255) / 256, 256>>>();
    hist_kernel<<<(N_EDGES + 255) / 256, 256>>>(ei);
    scan_kernel<<<1, 1024>>>();
    scatter_kernel<<<(N_EDGES + 255) / 256, 256>>>(ei);

    // projection (HMMA tensor cores) + attention logits
    dim3 ggrid((N_NODES + 127) / 128, 2);
    gemm_mma_kernel<<<ggrid, 256, SM_TOTAL>>>(x);
    alpha_kernel<<<(N_NODES * 32 + 255) / 256, 256>>>(x);

    // softmax + aggregate
    aggregate_kernel<<<(N_NODES * 32 + 255) / 256, 256>>>(bias, out);
}

// round 6
// speedup vs baseline: 1.4343x; 1.0001x over previous
#include <cuda_runtime.h>
#include <cuda_bf16.h>
#include <cstdint>

#define N_NODES 50000
#define N_EDGES 800000
#define IN_CH 256
#define OUT_CH 64
#define HEADS 4
#define HC 256  // HEADS*OUT_CH

// ---------------- scratch (device globals; no allocation allowed) ----------------
__device__ __align__(128) float g_xh[(size_t)N_NODES * HC];        // 51.2 MB projected features
__device__ __align__(128) float g_asrc[N_NODES * HEADS];
__device__ __align__(128) float g_adst[N_NODES * HEADS];
__device__ __align__(128) int   g_deg[N_NODES];
__device__ __align__(128) int   g_ctr[N_NODES];
__device__ __align__(128) int   g_rowptr[N_NODES + 1];
__device__ __align__(128) int   g_col[N_EDGES];
__device__ __align__(128) __nv_bfloat16 g_Whi[HC * IN_CH];         // [n][k] layout (k contiguous)
__device__ __align__(128) __nv_bfloat16 g_Wlo[HC * IN_CH];
__device__ __align__(128) float g_p[2 * IN_CH * HEADS];            // folded att: src then dst

// ---------------- small prep kernels ----------------

// Split W into bf16 hi/lo in [n][k] layout: n = h*64+c, k = f.
__global__ void prep_wsplit_kernel(const float* __restrict__ w) {
    int idx = blockIdx.x * blockDim.x + threadIdx.x;   // < 65536
    int n = idx >> 8;       // 0..255
    int k = idx & 255;      // 0..255
    int h = n >> 6;
    int c = n & 63;
    float v = w[h * (IN_CH * OUT_CH) + k * OUT_CH + c];
    __nv_bfloat16 hi = __float2bfloat16(v);
    __nv_bfloat16 lo = __float2bfloat16(v - __bfloat162float(hi));
    g_Whi[idx] = hi;
    g_Wlo[idx] = lo;
}

// p_src[f*4+h] = sum_c W[h][f][c] * att_src[h][c]  (same for dst)
__global__ void prep_p_kernel(const float* __restrict__ w,
                              const float* __restrict__ as,
                              const float* __restrict__ ad) {
    int t = blockIdx.x * blockDim.x + threadIdx.x;     // < 1024
    if (t >= IN_CH * HEADS) return;
    int f = t >> 2, h = t & 3;
    float ssum = 0.f, dsum = 0.f;
    const float* wr = w + h * (IN_CH * OUT_CH) + f * OUT_CH;
    const float* asr = as + h * OUT_CH;
    const float* adr = ad + h * OUT_CH;
#pragma unroll 8
    for (int c = 0; c < OUT_CH; c++) {
        float wv = wr[c];
        ssum += wv * asr[c];
        dsum += wv * adr[c];
    }
    g_p[t] = ssum;
    g_p[IN_CH * HEADS + t] = dsum;
}

__global__ void zero_kernel() {
    int i = blockIdx.x * blockDim.x + threadIdx.x;
    if (i < N_NODES) { g_deg[i] = 0; g_ctr[i] = 0; }
}

// ---------------- CSR build (edge_index is int32, [2][E]) ----------------

__global__ void hist_kernel(const int* __restrict__ ei) {
    int e = blockIdx.x * blockDim.x + threadIdx.x;
    if (e < N_EDGES) atomicAdd(&g_deg[ei[e]], 1);
}

__global__ void scan_kernel() {
    __shared__ int sh[1024];
    const int CH = (N_NODES + 1023) / 1024;  // 49
    int t = threadIdx.x;
    int beg = t * CH;
    int sum = 0;
    for (int i = 0; i < CH; i++) {
        int idx = beg + i;
        if (idx < N_NODES) sum += g_deg[idx];
    }
    sh[t] = sum;
    __syncthreads();
    for (int off = 1; off < 1024; off <<= 1) {
        int v = (t >= off) ? sh[t - off] : 0;
        __syncthreads();
        sh[t] += v;
        __syncthreads();
    }
    int run = (t == 0) ? 0 : sh[t - 1];
    for (int i = 0; i < CH; i++) {
        int idx = beg + i;
        if (idx < N_NODES) {
            g_rowptr[idx] = run;
            run += g_deg[idx];
        }
    }
    if (t == 0) g_rowptr[N_NODES] = N_EDGES;
}

__global__ void scatter_kernel(const int* __restrict__ ei) {
    int e = blockIdx.x * blockDim.x + threadIdx.x;
    if (e < N_EDGES) {
        int r = ei[e];
        int c = ei[N_EDGES + e];
        int p = g_rowptr[r] + atomicAdd(&g_ctr[r], 1);
        g_col[p] = c;
    }
}

// ---------------- HMMA projection GEMM: x [N,256] @ W^T -> g_xh [N,256] ----------------
// mma.sync.m16n8k16 bf16 with 2-term split: x@W ~= xhi@Whi + xhi@Wlo + xlo@Whi.
// CTA: 128 rows x 128 cols, 8 warps, each warp 32x64. K in 4 chunks of 64.
// SMEM row stride 144 B -> conflict-free fragment loads (banks 4*row+t all distinct).

#define GK 64
#define A_STRIDE 144                 // bytes per 64-col bf16 row (padded)
#define TILE_BYTES (128 * A_STRIDE)  // 18432
#define SM_AHI 0
#define SM_ALO (TILE_BYTES)
#define SM_BHI (2 * TILE_BYTES)
#define SM_BLO (3 * TILE_BYTES)
#define SM_TOTAL (4 * TILE_BYTES)    // 73728 B

__device__ __forceinline__ void mma16816(float* c, const uint32_t* a, uint32_t b0, uint32_t b1) {
    asm volatile(
        "mma.sync.aligned.m16n8k16.row.col.f32.bf16.bf16.f32 "
        "{%0,%1,%2,%3}, {%4,%5,%6,%7}, {%8,%9}, {%0,%1,%2,%3};"
        : "+f"(c[0]), "+f"(c[1]), "+f"(c[2]), "+f"(c[3])
        : "r"(a[0]), "r"(a[1]), "r"(a[2]), "r"(a[3]), "r"(b0), "r"(b1));
}

__global__ __launch_bounds__(256) void gemm_mma_kernel(const float* __restrict__ x) {
    extern __shared__ char smem[];
    int tid = threadIdx.x;
    int w = tid >> 5;
    int lane = tid & 31;
    int grp = lane >> 2;       // 0..7
    int t = lane & 3;          // 0..3
    int block_row = blockIdx.x * 128;
    int block_col = blockIdx.y * 128;

    int wm = (w & 3) * 32;     // warp row offset in CTA tile
    int wn = (w >> 2) * 64;    // warp col offset in CTA tile

    float acc[2][8][4];
#pragma unroll
    for (int mt = 0; mt < 2; mt++)
#pragma unroll
        for (int nt = 0; nt < 8; nt++)
#pragma unroll
            for (int q = 0; q < 4; q++) acc[mt][nt][q] = 0.f;

    for (int kc = 0; kc < IN_CH / GK; kc++) {
        // ---- load A chunk: x[block_row..+128][kc*64..+64] fp32 -> hi/lo bf16 ----
#pragma unroll
        for (int i = 0; i < 8; i++) {
            int id = tid + i * 256;          // 0..2047
            int row = id >> 4;               // 0..127
            int c4 = id & 15;                // float4 index within 64 cols
            int grow = block_row + row;
            float4 v = make_float4(0.f, 0.f, 0.f, 0.f);
            if (grow < N_NODES)
                v = *(const float4*)(x + (size_t)grow * IN_CH + kc * GK + c4 * 4);
            __nv_bfloat162 h01 = make_bfloat162(__float2bfloat16(v.x), __float2bfloat16(v.y));
            __nv_bfloat162 h23 = make_bfloat162(__float2bfloat16(v.z), __float2bfloat16(v.w));
            __nv_bfloat162 l01 = make_bfloat162(
                __float2bfloat16(v.x - __bfloat162float(h01.x)),
                __float2bfloat16(v.y - __bfloat162float(h01.y)));
            __nv_bfloat162 l23 = make_bfloat162(
                __float2bfloat16(v.z - __bfloat162float(h23.x)),
                __float2bfloat16(v.w - __bfloat162float(h23.y)));
            uint32_t bo = row * A_STRIDE + c4 * 8;
            *(uint2*)(smem + SM_AHI + bo) = make_uint2(*(uint32_t*)&h01, *(uint32_t*)&h23);
            *(uint2*)(smem + SM_ALO + bo) = make_uint2(*(uint32_t*)&l01, *(uint32_t*)&l23);
        }
        // ---- load B chunk: W{hi,lo}[block_col..+128][kc*64..+64] bf16 ----
#pragma unroll
        for (int i = 0; i < 4; i++) {
            int id = tid + i * 256;          // 0..1023 16B units
            int row = id >> 3;               // 0..127
            int u = id & 7;
            size_t goff = (size_t)(block_col + row) * IN_CH + kc * GK + u * 8;
            uint4 vh = *(const uint4*)(g_Whi + goff);
            uint4 vl = *(const uint4*)(g_Wlo + goff);
            uint32_t bo = row * A_STRIDE + u * 16;
            *(uint4*)(smem + SM_BHI + bo) = vh;
            *(uint4*)(smem + SM_BLO + bo) = vl;
        }
        __syncthreads();

        // ---- compute: 4 k16-steps ----
#pragma unroll
        for (int k16 = 0; k16 < 4; k16++) {
            int ko = k16 * 32;  // byte offset of this k16 within the 128B row
            uint32_t ah[2][4], al[2][4];
#pragma unroll
            for (int mt = 0; mt < 2; mt++) {
                int r0 = wm + mt * 16 + grp;
                uint32_t o00 = r0 * A_STRIDE + ko + t * 4;
                uint32_t o10 = (r0 + 8) * A_STRIDE + ko + t * 4;
                ah[mt][0] = *(const uint32_t*)(smem + SM_AHI + o00);
                ah[mt][1] = *(const uint32_t*)(smem + SM_AHI + o10);
                ah[mt][2] = *(const uint32_t*)(smem + SM_AHI + o00 + 16);
                ah[mt][3] = *(const uint32_t*)(smem + SM_AHI + o10 + 16);
                al[mt][0] = *(const uint32_t*)(smem + SM_ALO + o00);
                al[mt][1] = *(const uint32_t*)(smem + SM_ALO + o10);
                al[mt][2] = *(const uint32_t*)(smem + SM_ALO + o00 + 16);
                al[mt][3] = *(const uint32_t*)(smem + SM_ALO + o10 + 16);
            }
#pragma unroll
            for (int nt = 0; nt < 8; nt++) {
                int n0 = wn + nt * 8 + grp;
                uint32_t ob = n0 * A_STRIDE + ko + t * 4;
                uint32_t bh0 = *(const uint32_t*)(smem + SM_BHI + ob);
                uint32_t bh1 = *(const uint32_t*)(smem + SM_BHI + ob + 16);
                uint32_t bl0 = *(const uint32_t*)(smem + SM_BLO + ob);
                uint32_t bl1 = *(const uint32_t*)(smem + SM_BLO + ob + 16);
#pragma unroll
                for (int mt = 0; mt < 2; mt++) {
                    mma16816(acc[mt][nt], ah[mt], bh0, bh1);
                    mma16816(acc[mt][nt], ah[mt], bl0, bl1);
                    mma16816(acc[mt][nt], al[mt], bh0, bh1);
                }
            }
        }
        __syncthreads();
    }

    // ---- epilogue: write fragments to g_xh ----
#pragma unroll
    for (int mt = 0; mt < 2; mt++) {
        int gr0 = block_row + wm + mt * 16 + grp;
        int gr1 = gr0 + 8;
#pragma unroll
        for (int nt = 0; nt < 8; nt++) {
            int gc = block_col + wn + nt * 8 + t * 2;
            if (gr0 < N_NODES)
                *(float2*)(g_xh + (size_t)gr0 * HC + gc) = make_float2(acc[mt][nt][0], acc[mt][nt][1]);
            if (gr1 < N_NODES)
                *(float2*)(g_xh + (size_t)gr1 * HC + gc) = make_float2(acc[mt][nt][2], acc[mt][nt][3]);
        }
    }
}

// ---------------- attention logits: alpha = x @ p (one warp per node) ----------------

__global__ __launch_bounds__(256) void alpha_kernel(const float* __restrict__ x) {
    int warp = (blockIdx.x * blockDim.x + threadIdx.x) >> 5;
    int lane = threadIdx.x & 31;
    if (warp >= N_NODES) return;
    const float* xr = x + (size_t)warp * IN_CH;
    float s[4] = {0.f, 0.f, 0.f, 0.f};
    float d[4] = {0.f, 0.f, 0.f, 0.f};
    for (int f = lane; f < IN_CH; f += 32) {
        float xv = xr[f];
        const float* ps = g_p + f * 4;
        const float* pd = g_p + IN_CH * HEADS + f * 4;
#pragma unroll
        for (int h = 0; h < 4; h++) {
            s[h] += xv * ps[h];
            d[h] += xv * pd[h];
        }
    }
#pragma unroll
    for (int off = 16; off > 0; off >>= 1) {
#pragma unroll
        for (int h = 0; h < 4; h++) {
            s[h] += __shfl_xor_sync(0xffffffffu, s[h], off);
            d[h] += __shfl_xor_sync(0xffffffffu, d[h], off);
        }
    }
    if (lane == 0) {
#pragma unroll
        for (int h = 0; h < 4; h++) {
            g_asrc[warp * 4 + h] = s[h];
            g_adst[warp * 4 + h] = d[h];
        }
    }
}

// ---------------- softmax + weighted gather aggregation (one warp per node) ----------------

__global__ __launch_bounds__(256) void aggregate_kernel(const float* __restrict__ bias,
                                                        float* __restrict__ out) {
    int warp = (blockIdx.x * blockDim.x + threadIdx.x) >> 5;
    int lane = threadIdx.x & 31;
    if (warp >= N_NODES) return;
    int head = lane >> 3;
    float ah = g_asrc[warp * 4 + head];
    int beg = g_rowptr[warp];
    int end = g_rowptr[warp + 1];

    // pass 1: online softmax (running max + scaled sum)
    float m = -1e30f, s = 0.f;
    for (int e = beg; e < end; ++e) {
        int c = g_col[e];
        float a = ah + g_adst[c * 4 + head];
        a = (a > 0.f) ? a : 0.2f * a;
        float nm = fmaxf(m, a);
        s = s * __expf(m - nm) + __expf(a - nm);
        m = nm;
    }
    float inv = 1.0f / fmaxf(s, 1e-16f);

    // pass 2: weighted gather
    float acc[8];
#pragma unroll
    for (int i = 0; i < 8; i++) acc[i] = 0.f;
    int chbase = lane * 8;
    for (int e = beg; e < end; ++e) {
        int c = g_col[e];
        float a = ah + g_adst[c * 4 + head];
        a = (a > 0.f) ? a : 0.2f * a;
        float w = __expf(a - m) * inv;
        const float4* src = (const float4*)(g_xh + (size_t)c * HC + chbase);
        float4 v0 = src[0];
        float4 v1 = src[1];
        acc[0] += w * v0.x; acc[1] += w * v0.y; acc[2] += w * v0.z; acc[3] += w * v0.w;
        acc[4] += w * v1.x; acc[5] += w * v1.y; acc[6] += w * v1.z; acc[7] += w * v1.w;
    }

    float4 b0 = *(const float4*)(bias + chbase);
    float4 b1 = *(const float4*)(bias + chbase + 4);
    float* orow = out + (size_t)warp * HC + chbase;
    *(float4*)(orow)     = make_float4(acc[0] + b0.x, acc[1] + b0.y, acc[2] + b0.z, acc[3] + b0.w);
    *(float4*)(orow + 4) = make_float4(acc[4] + b1.x, acc[5] + b1.y, acc[6] + b1.z, acc[7] + b1.w);
}

// ---------------- launch ----------------

extern "C" void kernel_launch(void* const* d_in, const int* in_sizes, int n_in,
                              void* d_out, int out_size) {
    const float* x    = (const float*)d_in[0];
    const int*   ei   = (const int*)d_in[1];
    const float* w    = (const float*)d_in[2];
    const float* asv  = (const float*)d_in[3];
    const float* adv  = (const float*)d_in[4];
    const float* bias = (const float*)d_in[5];
    float* out = (float*)d_out;

    cudaFuncSetAttribute(gemm_mma_kernel, cudaFuncAttributeMaxDynamicSharedMemorySize, SM_TOTAL);

    // prep
    prep_wsplit_kernel<<<(HC * IN_CH) / 256, 256>>>(w);
    prep_p_kernel<<<4, 256>>>(w, asv, adv);

    // CSR build
    zero_kernel<<<(N_NODES + 255) / 256, 256>>>();
    hist_kernel<<<(N_EDGES + 255) / 256, 256>>>(ei);
    scan_kernel<<<1, 1024>>>();
    scatter_kernel<<<(N_EDGES + 255) / 256, 256>>>(ei);

    // projection (HMMA tensor cores) + attention logits
    dim3 ggrid((N_NODES + 127) / 128, 2);
    gemm_mma_kernel<<<ggrid, 256, SM_TOTAL>>>(x);
    alpha_kernel<<<(N_NODES * 32 + 255) / 256, 256>>>(x);

    // softmax + aggregate
    aggregate_kernel<<<(N_NODES * 32 + 255) / 256, 256>>>(bias, out);
}

// round 7
// speedup vs baseline: 1.4362x; 1.0013x over previous
#include <cuda_runtime.h>
#include <cuda_bf16.h>
#include <cstdint>

#define N_NODES 50000
#define N_EDGES 800000
#define IN_CH 256
#define OUT_CH 64
#define HEADS 4
#define HC 256  // HEADS*OUT_CH

// ---------------- scratch (device globals; no allocation allowed) ----------------
__device__ __align__(128) float g_xh[(size_t)N_NODES * HC];        // 51.2 MB projected features
__device__ __align__(128) float g_asrc[N_NODES * HEADS];
__device__ __align__(128) float g_adst[N_NODES * HEADS];
__device__ __align__(128) int   g_deg[N_NODES];
__device__ __align__(128) int   g_ctr[N_NODES];
__device__ __align__(128) int   g_rowptr[N_NODES + 1];
__device__ __align__(128) int   g_col[N_EDGES];
__device__ __align__(128) __nv_bfloat16 g_Whi[HC * IN_CH];         // [n][k] layout (k contiguous)
__device__ __align__(128) __nv_bfloat16 g_Wlo[HC * IN_CH];
__device__ __align__(128) float g_p[2 * IN_CH * HEADS];            // folded att: src then dst

// ---------------- small prep kernels ----------------

// Split W into bf16 hi/lo in [n][k] layout: n = h*64+c, k = f.
__global__ void prep_wsplit_kernel(const float* __restrict__ w) {
    int idx = blockIdx.x * blockDim.x + threadIdx.x;   // < 65536
    int n = idx >> 8;       // 0..255
    int k = idx & 255;      // 0..255
    int h = n >> 6;
    int c = n & 63;
    float v = w[h * (IN_CH * OUT_CH) + k * OUT_CH + c];
    __nv_bfloat16 hi = __float2bfloat16(v);
    __nv_bfloat16 lo = __float2bfloat16(v - __bfloat162float(hi));
    g_Whi[idx] = hi;
    g_Wlo[idx] = lo;
}

// p_src[f*4+h] = sum_c W[h][f][c] * att_src[h][c]  (same for dst)
__global__ void prep_p_kernel(const float* __restrict__ w,
                              const float* __restrict__ as,
                              const float* __restrict__ ad) {
    int t = blockIdx.x * blockDim.x + threadIdx.x;     // < 1024
    if (t >= IN_CH * HEADS) return;
    int f = t >> 2, h = t & 3;
    float ssum = 0.f, dsum = 0.f;
    const float* wr = w + h * (IN_CH * OUT_CH) + f * OUT_CH;
    const float* asr = as + h * OUT_CH;
    const float* adr = ad + h * OUT_CH;
#pragma unroll 8
    for (int c = 0; c < OUT_CH; c++) {
        float wv = wr[c];
        ssum += wv * asr[c];
        dsum += wv * adr[c];
    }
    g_p[t] = ssum;
    g_p[IN_CH * HEADS + t] = dsum;
}

__global__ void zero_kernel() {
    int i = blockIdx.x * blockDim.x + threadIdx.x;
    if (i < N_NODES) { g_deg[i] = 0; g_ctr[i] = 0; }
}

// ---------------- CSR build (edge_index is int32, [2][E]) ----------------

__global__ void hist_kernel(const int* __restrict__ ei) {
    int e = blockIdx.x * blockDim.x + threadIdx.x;
    if (e < N_EDGES) atomicAdd(&g_deg[ei[e]], 1);
}

__global__ void scan_kernel() {
    __shared__ int sh[1024];
    const int CH = (N_NODES + 1023) / 1024;  // 49
    int t = threadIdx.x;
    int beg = t * CH;
    int sum = 0;
    for (int i = 0; i < CH; i++) {
        int idx = beg + i;
        if (idx < N_NODES) sum += g_deg[idx];
    }
    sh[t] = sum;
    __syncthreads();
    for (int off = 1; off < 1024; off <<= 1) {
        int v = (t >= off) ? sh[t - off] : 0;
        __syncthreads();
        sh[t] += v;
        __syncthreads();
    }
    int run = (t == 0) ? 0 : sh[t - 1];
    for (int i = 0; i < CH; i++) {
        int idx = beg + i;
        if (idx < N_NODES) {
            g_rowptr[idx] = run;
            run += g_deg[idx];
        }
    }
    if (t == 0) g_rowptr[N_NODES] = N_EDGES;
}

__global__ void scatter_kernel(const int* __restrict__ ei) {
    int e = blockIdx.x * blockDim.x + threadIdx.x;
    if (e < N_EDGES) {
        int r = ei[e];
        int c = ei[N_EDGES + e];
        int p = g_rowptr[r] + atomicAdd(&g_ctr[r], 1);
        g_col[p] = c;
    }
}

// ---------------- HMMA projection GEMM: x [N,256] @ W^T -> g_xh [N,256] ----------------
// mma.sync.m16n8k16 bf16 with 2-term split: x@W ~= xhi@Whi + xhi@Wlo + xlo@Whi.
// CTA: 128 rows x 128 cols, 8 warps, each warp 32x64. K in 4 chunks of 64.
// SMEM row stride 144 B -> conflict-free fragment loads (banks 4*row+t all distinct).

#define GK 64
#define A_STRIDE 144                 // bytes per 64-col bf16 row (padded)
#define TILE_BYTES (128 * A_STRIDE)  // 18432
#define SM_AHI 0
#define SM_ALO (TILE_BYTES)
#define SM_BHI (2 * TILE_BYTES)
#define SM_BLO (3 * TILE_BYTES)
#define SM_TOTAL (4 * TILE_BYTES)    // 73728 B

__device__ __forceinline__ void mma16816(float* c, const uint32_t* a, uint32_t b0, uint32_t b1) {
    asm volatile(
        "mma.sync.aligned.m16n8k16.row.col.f32.bf16.bf16.f32 "
        "{%0,%1,%2,%3}, {%4,%5,%6,%7}, {%8,%9}, {%0,%1,%2,%3};"
        : "+f"(c[0]), "+f"(c[1]), "+f"(c[2]), "+f"(c[3])
        : "r"(a[0]), "r"(a[1]), "r"(a[2]), "r"(a[3]), "r"(b0), "r"(b1));
}

__global__ __launch_bounds__(256) void gemm_mma_kernel(const float* __restrict__ x) {
    extern __shared__ char smem[];
    int tid = threadIdx.x;
    int w = tid >> 5;
    int lane = tid & 31;
    int grp = lane >> 2;       // 0..7
    int t = lane & 3;          // 0..3
    int block_row = blockIdx.x * 128;
    int block_col = blockIdx.y * 128;

    int wm = (w & 3) * 32;     // warp row offset in CTA tile
    int wn = (w >> 2) * 64;    // warp col offset in CTA tile

    float acc[2][8][4];
#pragma unroll
    for (int mt = 0; mt < 2; mt++)
#pragma unroll
        for (int nt = 0; nt < 8; nt++)
#pragma unroll
            for (int q = 0; q < 4; q++) acc[mt][nt][q] = 0.f;

    for (int kc = 0; kc < IN_CH / GK; kc++) {
        // ---- load A chunk: x[block_row..+128][kc*64..+64] fp32 -> hi/lo bf16 ----
#pragma unroll
        for (int i = 0; i < 8; i++) {
            int id = tid + i * 256;          // 0..2047
            int row = id >> 4;               // 0..127
            int c4 = id & 15;                // float4 index within 64 cols
            int grow = block_row + row;
            float4 v = make_float4(0.f, 0.f, 0.f, 0.f);
            if (grow < N_NODES)
                v = *(const float4*)(x + (size_t)grow * IN_CH + kc * GK + c4 * 4);
            __nv_bfloat162 h01 = make_bfloat162(__float2bfloat16(v.x), __float2bfloat16(v.y));
            __nv_bfloat162 h23 = make_bfloat162(__float2bfloat16(v.z), __float2bfloat16(v.w));
            __nv_bfloat162 l01 = make_bfloat162(
                __float2bfloat16(v.x - __bfloat162float(h01.x)),
                __float2bfloat16(v.y - __bfloat162float(h01.y)));
            __nv_bfloat162 l23 = make_bfloat162(
                __float2bfloat16(v.z - __bfloat162float(h23.x)),
                __float2bfloat16(v.w - __bfloat162float(h23.y)));
            uint32_t bo = row * A_STRIDE + c4 * 8;
            *(uint2*)(smem + SM_AHI + bo) = make_uint2(*(uint32_t*)&h01, *(uint32_t*)&h23);
            *(uint2*)(smem + SM_ALO + bo) = make_uint2(*(uint32_t*)&l01, *(uint32_t*)&l23);
        }
        // ---- load B chunk: W{hi,lo}[block_col..+128][kc*64..+64] bf16 ----
#pragma unroll
        for (int i = 0; i < 4; i++) {
            int id = tid + i * 256;          // 0..1023 16B units
            int row = id >> 3;               // 0..127
            int u = id & 7;
            size_t goff = (size_t)(block_col + row) * IN_CH + kc * GK + u * 8;
            uint4 vh = *(const uint4*)(g_Whi + goff);
            uint4 vl = *(const uint4*)(g_Wlo + goff);
            uint32_t bo = row * A_STRIDE + u * 16;
            *(uint4*)(smem + SM_BHI + bo) = vh;
            *(uint4*)(smem + SM_BLO + bo) = vl;
        }
        __syncthreads();

        // ---- compute: 4 k16-steps ----
#pragma unroll
        for (int k16 = 0; k16 < 4; k16++) {
            int ko = k16 * 32;  // byte offset of this k16 within the 128B row
            uint32_t ah[2][4], al[2][4];
#pragma unroll
            for (int mt = 0; mt < 2; mt++) {
                int r0 = wm + mt * 16 + grp;
                uint32_t o00 = r0 * A_STRIDE + ko + t * 4;
                uint32_t o10 = (r0 + 8) * A_STRIDE + ko + t * 4;
                ah[mt][0] = *(const uint32_t*)(smem + SM_AHI + o00);
                ah[mt][1] = *(const uint32_t*)(smem + SM_AHI + o10);
                ah[mt][2] = *(const uint32_t*)(smem + SM_AHI + o00 + 16);
                ah[mt][3] = *(const uint32_t*)(smem + SM_AHI + o10 + 16);
                al[mt][0] = *(const uint32_t*)(smem + SM_ALO + o00);
                al[mt][1] = *(const uint32_t*)(smem + SM_ALO + o10);
                al[mt][2] = *(const uint32_t*)(smem + SM_ALO + o00 + 16);
                al[mt][3] = *(const uint32_t*)(smem + SM_ALO + o10 + 16);
            }
#pragma unroll
            for (int nt = 0; nt < 8; nt++) {
                int n0 = wn + nt * 8 + grp;
                uint32_t ob = n0 * A_STRIDE + ko + t * 4;
                uint32_t bh0 = *(const uint32_t*)(smem + SM_BHI + ob);
                uint32_t bh1 = *(const uint32_t*)(smem + SM_BHI + ob + 16);
                uint32_t bl0 = *(const uint32_t*)(smem + SM_BLO + ob);
                uint32_t bl1 = *(const uint32_t*)(smem + SM_BLO + ob + 16);
#pragma unroll
                for (int mt = 0; mt < 2; mt++) {
                    mma16816(acc[mt][nt], ah[mt], bh0, bh1);
                    mma16816(acc[mt][nt], ah[mt], bl0, bl1);
                    mma16816(acc[mt][nt], al[mt], bh0, bh1);
                }
            }
        }
        __syncthreads();
    }

    // ---- epilogue: write fragments to g_xh ----
#pragma unroll
    for (int mt = 0; mt < 2; mt++) {
        int gr0 = block_row + wm + mt * 16 + grp;
        int gr1 = gr0 + 8;
#pragma unroll
        for (int nt = 0; nt < 8; nt++) {
            int gc = block_col + wn + nt * 8 + t * 2;
            if (gr0 < N_NODES)
                *(float2*)(g_xh + (size_t)gr0 * HC + gc) = make_float2(acc[mt][nt][0], acc[mt][nt][1]);
            if (gr1 < N_NODES)
                *(float2*)(g_xh + (size_t)gr1 * HC + gc) = make_float2(acc[mt][nt][2], acc[mt][nt][3]);
        }
    }
}

// ---------------- attention logits: alpha = x @ p (one warp per node) ----------------

__global__ __launch_bounds__(256) void alpha_kernel(const float* __restrict__ x) {
    int warp = (blockIdx.x * blockDim.x + threadIdx.x) >> 5;
    int lane = threadIdx.x & 31;
    if (warp >= N_NODES) return;
    const float* xr = x + (size_t)warp * IN_CH;
    float s[4] = {0.f, 0.f, 0.f, 0.f};
    float d[4] = {0.f, 0.f, 0.f, 0.f};
    for (int f = lane; f < IN_CH; f += 32) {
        float xv = xr[f];
        const float* ps = g_p + f * 4;
        const float* pd = g_p + IN_CH * HEADS + f * 4;
#pragma unroll
        for (int h = 0; h < 4; h++) {
            s[h] += xv * ps[h];
            d[h] += xv * pd[h];
        }
    }
#pragma unroll
    for (int off = 16; off > 0; off >>= 1) {
#pragma unroll
        for (int h = 0; h < 4; h++) {
            s[h] += __shfl_xor_sync(0xffffffffu, s[h], off);
            d[h] += __shfl_xor_sync(0xffffffffu, d[h], off);
        }
    }
    if (lane == 0) {
#pragma unroll
        for (int h = 0; h < 4; h++) {
            g_asrc[warp * 4 + h] = s[h];
            g_adst[warp * 4 + h] = d[h];
        }
    }
}

// ---------------- softmax + weighted gather aggregation (one warp per node) ----------------

__global__ __launch_bounds__(256) void aggregate_kernel(const float* __restrict__ bias,
                                                        float* __restrict__ out) {
    int warp = (blockIdx.x * blockDim.x + threadIdx.x) >> 5;
    int lane = threadIdx.x & 31;
    if (warp >= N_NODES) return;
    int head = lane >> 3;
    float ah = g_asrc[warp * 4 + head];
    int beg = g_rowptr[warp];
    int end = g_rowptr[warp + 1];

    // pass 1: online softmax (running max + scaled sum)
    float m = -1e30f, s = 0.f;
    for (int e = beg; e < end; ++e) {
        int c = g_col[e];
        float a = ah + g_adst[c * 4 + head];
        a = (a > 0.f) ? a : 0.2f * a;
        float nm = fmaxf(m, a);
        s = s * __expf(m - nm) + __expf(a - nm);
        m = nm;
    }
    float inv = 1.0f / fmaxf(s, 1e-16f);

    // pass 2: weighted gather
    float acc[8];
#pragma unroll
    for (int i = 0; i < 8; i++) acc[i] = 0.f;
    int chbase = lane * 8;
    for (int e = beg; e < end; ++e) {
        int c = g_col[e];
        float a = ah + g_adst[c * 4 + head];
        a = (a > 0.f) ? a : 0.2f * a;
        float w = __expf(a - m) * inv;
        const float4* src = (const float4*)(g_xh + (size_t)c * HC + chbase);
        float4 v0 = src[0];
        float4 v1 = src[1];
        acc[0] += w * v0.x; acc[1] += w * v0.y; acc[2] += w * v0.z; acc[3] += w * v0.w;
        acc[4] += w * v1.x; acc[5] += w * v1.y; acc[6] += w * v1.z; acc[7] += w * v1.w;
    }

    float4 b0 = *(const float4*)(bias + chbase);
    float4 b1 = *(const float4*)(bias + chbase + 4);
    float* orow = out + (size_t)warp * HC + chbase;
    *(float4*)(orow)     = make_float4(acc[0] + b0.x, acc[1] + b0.y, acc[2] + b0.z, acc[3] + b0.w);
    *(float4*)(orow + 4) = make_float4(acc[4] + b1.x, acc[5] + b1.y, acc[6] + b1.z, acc[7] + b1.w);
}

// ---------------- launch ----------------

extern "C" void kernel_launch(void* const* d_in, const int* in_sizes, int n_in,
                              void* d_out, int out_size) {
    const float* x    = (const float*)d_in[0];
    const int*   ei   = (const int*)d_in[1];
    const float* w    = (const float*)d_in[2];
    const float* asv  = (const float*)d_in[3];
    const float* adv  = (const float*)d_in[4];
    const float* bias = (const float*)d_in[5];
    float* out = (float*)d_out;

    cudaFuncSetAttribute(gemm_mma_kernel, cudaFuncAttributeMaxDynamicSharedMemorySize, SM_TOTAL);

    // prep
    prep_wsplit_kernel<<<(HC * IN_CH) / 256, 256>>>(w);
    prep_p_kernel<<<4, 256>>>(w, asv, adv);

    // CSR build
    zero_kernel<<<(N_NODES + 255) / 256, 256>>>();
    hist_kernel<<<(N_EDGES + 255) / 256, 256>>>(ei);
    scan_kernel<<<1, 1024>>>();
    scatter_kernel<<<(N_EDGES + 255) / 256, 256>>>(ei);

    // projection (HMMA tensor cores) + attention logits
    dim3 ggrid((N_NODES + 127) / 128, 2);
    gemm_mma_kernel<<<ggrid, 256, SM_TOTAL>>>(x);
    alpha_kernel<<<(N_NODES * 32 + 255) / 256, 256>>>(x);

    // softmax + aggregate
    aggregate_kernel<<<(N_NODES * 32 + 255) / 256, 256>>>(bias, out);
}